// round 3
// baseline (speedup 1.0000x reference)
#include <cuda_runtime.h>
#include <cuda_bf16.h>
#include <math.h>

// Problem constants
#define B_     64
#define S_     2048
#define D_     768
#define L_     2
#define POOL_  30
#define LEN_   5
#define TOPK_  5
#define SS_    32           // S split count
#define SCHUNK_ (S_ / SS_)  // 64

// Output layout (flattened tuple, fp32):
#define NB_ELEMS   (L_ * B_ * (TOPK_*LEN_) * D_)   // 2457600
#define OFF_SB     0
#define OFF_TB     (NB_ELEMS)
#define OFF_SSIM   (2 * NB_ELEMS)
#define OFF_TSIM   (OFF_SSIM + B_ * POOL_)
#define OFF_SRED   (OFF_TSIM + B_ * POOL_)
#define OFF_TRED   (OFF_SRED + 1)

// Device scratch
__device__ float g_partial[SS_ * B_ * D_];   // 6 MB partial sums
__device__ float g_stop[B_];
__device__ float g_ttop[B_];

// ---------------------------------------------------------------------------
// Kernel A: partial mean over S chunks.  grid (B, SS), block 192 (float4/d)
// 2048 blocks for high residency; streaming loads (x touched exactly once).
// ---------------------------------------------------------------------------
__global__ void __launch_bounds__(192) k_mean_partial(const float* __restrict__ x) {
    int b  = blockIdx.x;
    int ss = blockIdx.y;
    int d4 = threadIdx.x;                     // 0..191, each owns 4 d's
    const float4* xp = reinterpret_cast<const float4*>(x)
                     + ((size_t)(b * S_ + ss * SCHUNK_)) * (D_ / 4) + d4;
    float4 acc = make_float4(0.f, 0.f, 0.f, 0.f);
#pragma unroll 8
    for (int s = 0; s < SCHUNK_; ++s) {
        float4 v = __ldcs(&xp[(size_t)s * (D_ / 4)]);
        acc.x += v.x; acc.y += v.y; acc.z += v.z; acc.w += v.w;
    }
    reinterpret_cast<float4*>(g_partial)[(ss * B_ + b) * (D_ / 4) + d4] = acc;
}

// ---------------------------------------------------------------------------
// Block reduce helper (256 threads)
// ---------------------------------------------------------------------------
__device__ __forceinline__ float block_reduce_256(float v, float* red) {
    int lane = threadIdx.x & 31, w = threadIdx.x >> 5;
#pragma unroll
    for (int o = 16; o; o >>= 1) v += __shfl_down_sync(0xffffffffu, v, o);
    if (lane == 0) red[w] = v;
    __syncthreads();
    if (w == 0) {
        v = (lane < 8) ? red[lane] : 0.f;
#pragma unroll
        for (int o = 4; o; o >>= 1) v += __shfl_down_sync(0xffffffffu, v, o);
        if (lane == 0) red[0] = v;
    }
    __syncthreads();
    return red[0];
}

// ---------------------------------------------------------------------------
// Kernel C: per-batch: mean -> norm -> 60 sims -> top-5 -> GATHER (fused).
// grid 64, block 256. Block b gathers its own batch's prompt rows right
// after its own top-5 — no global sync needed.
// ---------------------------------------------------------------------------
__global__ void __launch_bounds__(256) k_finalize(const float* __restrict__ skey,
                                                  const float* __restrict__ tkey,
                                                  const float* __restrict__ sp,
                                                  const float* __restrict__ tp,
                                                  float* __restrict__ out) {
    int b = blockIdx.x;
    __shared__ float xn[D_];
    __shared__ float sim[2 * POOL_];
    __shared__ float red[8];
    __shared__ int   sidx[2][TOPK_];

    // mean over 32 partials (float4 lanes on threads 0..191)
    float sq = 0.f;
    if (threadIdx.x < 192) {
        int d4 = threadIdx.x;
        float4 s = make_float4(0.f, 0.f, 0.f, 0.f);
#pragma unroll
        for (int ss = 0; ss < SS_; ++ss) {
            float4 v = reinterpret_cast<const float4*>(g_partial)[(ss * B_ + b) * (D_ / 4) + d4];
            s.x += v.x; s.y += v.y; s.z += v.z; s.w += v.w;
        }
        const float scale = 1.f / (float)S_;
        s.x *= scale; s.y *= scale; s.z *= scale; s.w *= scale;
        reinterpret_cast<float4*>(xn)[d4] = s;
        sq = s.x * s.x + s.y * s.y + s.z * s.z + s.w * s.w;
    }
    __syncthreads();
    float total = block_reduce_256(sq, red);
    float inv = rsqrtf(fmaxf(total, 1e-12f));
    if (threadIdx.x < 192) {
        float4 v = reinterpret_cast<float4*>(xn)[threadIdx.x];
        v.x *= inv; v.y *= inv; v.z *= inv; v.w *= inv;
        reinterpret_cast<float4*>(xn)[threadIdx.x] = v;
    }
    __syncthreads();

    // 60 dots: warp per key; key normalized inline via rsqrt(||k||^2)
    int lane = threadIdx.x & 31, w = threadIdx.x >> 5;   // 8 warps
    for (int key = w; key < 2 * POOL_; key += 8) {
        const float* kp = (key < POOL_) ? (skey + key * D_)
                                        : (tkey + (key - POOL_) * D_);
        float dot = 0.f, kk = 0.f;
#pragma unroll
        for (int i = 0; i < D_ / 32; ++i) {
            int d = lane + i * 32;
            float kv = __ldg(&kp[d]);
            dot += kv * xn[d];
            kk  += kv * kv;
        }
#pragma unroll
        for (int o = 16; o; o >>= 1) {
            dot += __shfl_down_sync(0xffffffffu, dot, o);
            kk  += __shfl_down_sync(0xffffffffu, kk, o);
        }
        if (lane == 0) {
            float sv = dot * rsqrtf(fmaxf(kk, 1e-12f));
            sim[key] = sv;
            if (key < POOL_) out[OFF_SSIM + b * POOL_ + key] = sv;
            else             out[OFF_TSIM + b * POOL_ + (key - POOL_)] = sv;
        }
    }
    __syncthreads();

    // top-5 (threads 0 and 1); strict '>' keeps lowest index on ties
    if (threadIdx.x < 2) {
        const float* sm = sim + threadIdx.x * POOL_;
        float* gt = (threadIdx.x == 0) ? g_stop : g_ttop;
        float loc[POOL_];
#pragma unroll
        for (int i = 0; i < POOL_; ++i) loc[i] = sm[i];
        float topsum = 0.f;
#pragma unroll
        for (int k = 0; k < TOPK_; ++k) {
            int   bj = 0;
            float bv = loc[0];
#pragma unroll
            for (int i = 1; i < POOL_; ++i) {
                if (loc[i] > bv) { bv = loc[i]; bj = i; }
            }
            sidx[threadIdx.x][k] = bj;
            topsum += bv;
            loc[bj] = -INFINITY;
        }
        gt[b] = topsum;
    }
    __syncthreads();

    // Fused gather for this batch: 2 tensors x 2 l x 5 k x 5 t x 192 float4
    const int ROWF4 = D_ / 4;                           // 192
    const int TOT   = 2 * L_ * TOPK_ * LEN_ * ROWF4;    // 19200
    for (int i = threadIdx.x; i < TOT; i += 256) {
        int col = i % ROWF4;
        int row = i / ROWF4;            // 0..99
        int tensor = row / (L_ * TOPK_ * LEN_);   // /50
        int r  = row % (L_ * TOPK_ * LEN_);
        int l  = r / (TOPK_ * LEN_);              // /25
        int r2 = r % (TOPK_ * LEN_);
        int k  = r2 / LEN_;
        int t  = r2 % LEN_;
        int idx = sidx[tensor][k];
        const float* srcbase = tensor ? tp : sp;
        const float4* src = reinterpret_cast<const float4*>(
            srcbase + ((size_t)((l * POOL_ + idx) * LEN_ + t)) * D_);
        float4* dst = reinterpret_cast<float4*>(
            out + (tensor ? OFF_TB : OFF_SB)
                + ((size_t)((l * B_ + b) * (TOPK_ * LEN_) + r2)) * D_);
        __stcs(&dst[col], __ldg(&src[col]));
    }
}

// ---------------------------------------------------------------------------
// Kernel E: reduce-sim scalars (needs all finalize blocks done)
// ---------------------------------------------------------------------------
__global__ void k_scalars(float* __restrict__ out) {
    if (threadIdx.x < 2) {
        const float* g = (threadIdx.x == 0) ? g_stop : g_ttop;
        float s = 0.f;
        for (int i = 0; i < B_; ++i) s += g[i];
        out[(threadIdx.x == 0) ? OFF_SRED : OFF_TRED] = s / (float)B_;
    }
}

// ---------------------------------------------------------------------------
extern "C" void kernel_launch(void* const* d_in, const int* in_sizes, int n_in,
                              void* d_out, int out_size) {
    (void)in_sizes; (void)n_in; (void)out_size;
    const float* x_embed  = (const float*)d_in[0];
    const float* s_prompt = (const float*)d_in[1];
    const float* t_prompt = (const float*)d_in[2];
    const float* s_key    = (const float*)d_in[3];
    const float* t_key    = (const float*)d_in[4];
    float* out = (float*)d_out;

    k_mean_partial<<<dim3(B_, SS_), 192>>>(x_embed);
    k_finalize<<<B_, 256>>>(s_key, t_key, s_prompt, t_prompt, out);
    k_scalars<<<1, 32>>>(out);
}

// round 4
// speedup vs baseline: 1.1020x; 1.1020x over previous
#include <cuda_runtime.h>
#include <cuda_bf16.h>
#include <math.h>

// Problem constants
#define B_     64
#define S_     2048
#define D_     768
#define L_     2
#define POOL_  30
#define LEN_   5
#define TOPK_  5
#define SS_    16           // S split count
#define SCHUNK_ (S_ / SS_)  // 128

// Output layout (flattened tuple, fp32):
#define NB_ELEMS   (L_ * B_ * (TOPK_*LEN_) * D_)   // 2457600
#define OFF_SB     0
#define OFF_TB     (NB_ELEMS)
#define OFF_SSIM   (2 * NB_ELEMS)
#define OFF_TSIM   (OFF_SSIM + B_ * POOL_)
#define OFF_SRED   (OFF_TSIM + B_ * POOL_)
#define OFF_TRED   (OFF_SRED + 1)

// Device scratch
__device__ float g_partial[SS_ * B_ * D_];   // 3 MB partial sums
__device__ int   g_sidx[B_ * TOPK_];
__device__ int   g_tidx[B_ * TOPK_];
__device__ float g_stop[B_];
__device__ float g_ttop[B_];

// ---------------------------------------------------------------------------
// Kernel A: partial mean over S chunks.  grid (B, SS), block 192 (float4/d)
// Streaming loads (x touched exactly once); deep unroll for MLP.
// ---------------------------------------------------------------------------
__global__ void __launch_bounds__(192) k_mean_partial(const float* __restrict__ x) {
    int b  = blockIdx.x;
    int ss = blockIdx.y;
    int d4 = threadIdx.x;                     // 0..191, each owns 4 d's
    const float4* xp = reinterpret_cast<const float4*>(x)
                     + ((size_t)(b * S_ + ss * SCHUNK_)) * (D_ / 4) + d4;
    float4 acc = make_float4(0.f, 0.f, 0.f, 0.f);
#pragma unroll 16
    for (int s = 0; s < SCHUNK_; ++s) {
        float4 v = __ldcs(&xp[(size_t)s * (D_ / 4)]);
        acc.x += v.x; acc.y += v.y; acc.z += v.z; acc.w += v.w;
    }
    reinterpret_cast<float4*>(g_partial)[(ss * B_ + b) * (D_ / 4) + d4] = acc;
}

// ---------------------------------------------------------------------------
// Block reduce helper (256 threads)
// ---------------------------------------------------------------------------
__device__ __forceinline__ float block_reduce_256(float v, float* red) {
    int lane = threadIdx.x & 31, w = threadIdx.x >> 5;
#pragma unroll
    for (int o = 16; o; o >>= 1) v += __shfl_down_sync(0xffffffffu, v, o);
    if (lane == 0) red[w] = v;
    __syncthreads();
    if (w == 0) {
        v = (lane < 8) ? red[lane] : 0.f;
#pragma unroll
        for (int o = 4; o; o >>= 1) v += __shfl_down_sync(0xffffffffu, v, o);
        if (lane == 0) red[0] = v;
    }
    __syncthreads();
    return red[0];
}

// ---------------------------------------------------------------------------
// Kernel C: finalize per-batch: mean -> norm -> 60 sims -> top-5.
// grid 64, block 256. Keys normalized inline: dot(k,x)*rsqrt(||k||^2).
// ---------------------------------------------------------------------------
__global__ void __launch_bounds__(256) k_finalize(const float* __restrict__ skey,
                                                  const float* __restrict__ tkey,
                                                  float* __restrict__ out) {
    int b = blockIdx.x;
    __shared__ float xn[D_];
    __shared__ float sim[2 * POOL_];
    __shared__ float red[8];

    // mean over 16 partials (float4 lanes on threads 0..191)
    float sq = 0.f;
    if (threadIdx.x < 192) {
        int d4 = threadIdx.x;
        float4 s = make_float4(0.f, 0.f, 0.f, 0.f);
#pragma unroll
        for (int ss = 0; ss < SS_; ++ss) {
            float4 v = reinterpret_cast<const float4*>(g_partial)[(ss * B_ + b) * (D_ / 4) + d4];
            s.x += v.x; s.y += v.y; s.z += v.z; s.w += v.w;
        }
        const float scale = 1.f / (float)S_;
        s.x *= scale; s.y *= scale; s.z *= scale; s.w *= scale;
        reinterpret_cast<float4*>(xn)[d4] = s;
        sq = s.x * s.x + s.y * s.y + s.z * s.z + s.w * s.w;
    }
    __syncthreads();
    float total = block_reduce_256(sq, red);
    float inv = rsqrtf(fmaxf(total, 1e-12f));
    if (threadIdx.x < 192) {
        float4 v = reinterpret_cast<float4*>(xn)[threadIdx.x];
        v.x *= inv; v.y *= inv; v.z *= inv; v.w *= inv;
        reinterpret_cast<float4*>(xn)[threadIdx.x] = v;
    }
    __syncthreads();

    // 60 dots: warp per key, round-robin
    int lane = threadIdx.x & 31, w = threadIdx.x >> 5;   // 8 warps
    for (int key = w; key < 2 * POOL_; key += 8) {
        const float* kp = (key < POOL_) ? (skey + key * D_)
                                        : (tkey + (key - POOL_) * D_);
        float dot = 0.f, kk = 0.f;
#pragma unroll
        for (int i = 0; i < D_ / 32; ++i) {
            int d = lane + i * 32;
            float kv = __ldg(&kp[d]);
            dot += kv * xn[d];
            kk  += kv * kv;
        }
#pragma unroll
        for (int o = 16; o; o >>= 1) {
            dot += __shfl_down_sync(0xffffffffu, dot, o);
            kk  += __shfl_down_sync(0xffffffffu, kk, o);
        }
        if (lane == 0) {
            float sv = dot * rsqrtf(fmaxf(kk, 1e-12f));
            sim[key] = sv;
            if (key < POOL_) out[OFF_SSIM + b * POOL_ + key] = sv;
            else             out[OFF_TSIM + b * POOL_ + (key - POOL_)] = sv;
        }
    }
    __syncthreads();

    // top-5 (threads 0 and 1); strict '>' keeps lowest index on ties
    if (threadIdx.x < 2) {
        const float* sm = sim + threadIdx.x * POOL_;
        int*   gi = (threadIdx.x == 0) ? g_sidx : g_tidx;
        float* gt = (threadIdx.x == 0) ? g_stop : g_ttop;
        float loc[POOL_];
#pragma unroll
        for (int i = 0; i < POOL_; ++i) loc[i] = sm[i];
        float topsum = 0.f;
#pragma unroll
        for (int k = 0; k < TOPK_; ++k) {
            int   bj = 0;
            float bv = loc[0];
#pragma unroll
            for (int i = 1; i < POOL_; ++i) {
                if (loc[i] > bv) { bv = loc[i]; bj = i; }
            }
            gi[b * TOPK_ + k] = bj;
            topsum += bv;
            loc[bj] = -INFINITY;
        }
        gt[b] = topsum;
    }
}

// ---------------------------------------------------------------------------
// Kernel D: gather prompts + scalars.
// grid 640 = (tensor 2) x (b 64) x (k 5); block 192.
// Thread t owns float4 column t; loops over the 10 (l,t) rows — no divisions
// in the hot loop. Block 0 threads 0/1 emit the reduce-sim scalars.
// ---------------------------------------------------------------------------
__global__ void __launch_bounds__(192) k_gather(const float* __restrict__ sp,
                                                const float* __restrict__ tp,
                                                float* __restrict__ out) {
    int bi = blockIdx.x;
    int tensor = bi / (B_ * TOPK_);
    int rem    = bi % (B_ * TOPK_);
    int b  = rem / TOPK_;
    int k  = rem % TOPK_;

    if (bi == 0 && threadIdx.x < 2) {
        const float* g = (threadIdx.x == 0) ? g_stop : g_ttop;
        float s = 0.f;
        for (int i = 0; i < B_; ++i) s += g[i];
        out[(threadIdx.x == 0) ? OFF_SRED : OFF_TRED] = s / (float)B_;
    }

    int idx = tensor ? g_tidx[b * TOPK_ + k] : g_sidx[b * TOPK_ + k];
    const float* srcbase = tensor ? tp : sp;
    float* outbase = out + (tensor ? OFF_TB : OFF_SB);

    const int ROWF4 = D_ / 4;   // 192
    int col = threadIdx.x;
    // src row (l, idx, t): ((l*POOL + idx)*LEN + t) * D
    // dst row (l, b, k, t): ((l*B + b)*25 + k*5 + t) * D
#pragma unroll
    for (int l = 0; l < L_; ++l) {
        const float4* src = reinterpret_cast<const float4*>(
            srcbase + ((size_t)((l * POOL_ + idx) * LEN_)) * D_) + col;
        float4* dst = reinterpret_cast<float4*>(
            outbase + ((size_t)((l * B_ + b) * (TOPK_ * LEN_) + k * LEN_)) * D_) + col;
#pragma unroll
        for (int t = 0; t < LEN_; ++t) {
            __stcs(&dst[t * ROWF4], __ldg(&src[t * ROWF4]));
        }
    }
}

// ---------------------------------------------------------------------------
extern "C" void kernel_launch(void* const* d_in, const int* in_sizes, int n_in,
                              void* d_out, int out_size) {
    (void)in_sizes; (void)n_in; (void)out_size;
    const float* x_embed  = (const float*)d_in[0];
    const float* s_prompt = (const float*)d_in[1];
    const float* t_prompt = (const float*)d_in[2];
    const float* s_key    = (const float*)d_in[3];
    const float* t_key    = (const float*)d_in[4];
    float* out = (float*)d_out;

    k_mean_partial<<<dim3(B_, SS_), 192>>>(x_embed);
    k_finalize<<<B_, 256>>>(s_key, t_key, out);
    k_gather<<<2 * B_ * TOPK_, 192>>>(s_prompt, t_prompt, out);
}